// round 13
// baseline (speedup 1.0000x reference)
#include <cuda_runtime.h>
#include <cstddef>
#include <cstdint>

#define BATCH 64
#define SEQ   2048
#define DIM   512
#define NFINE 16
#define MSPAN 512
#define GRID  (148 * 3)

typedef unsigned long long u64;

// Blackwell packed fp32x2 math (SASS FFMA2/FADD2) — PTX-only.
#define FMA2(d,a,b,c) asm("fma.rn.f32x2 %0, %1, %2, %3;" : "=l"(d) : "l"(a), "l"(b), "l"(c))
#define ADD2(d,a,b)   asm("add.rn.f32x2 %0, %1, %2;" : "=l"(d) : "l"(a), "l"(b))

#define ACC_ROW(F, a, b, c, d)                         \
    do {                                               \
        ADD2(F[0], F[0], (a).x); ADD2(F[1], F[1], (a).y); \
        ADD2(F[2], F[2], (b).x); ADD2(F[3], F[3], (b).y); \
        ADD2(F[4], F[4], (c).x); ADD2(F[5], F[5], (c).y); \
        ADD2(F[6], F[6], (d).x); ADD2(F[7], F[7], (d).y); \
    } while (0)

// [0]=total spans, [1]=work ticket, [2]=unused, [3]=index-done counter
__device__ int  g_ctr[4];
__device__ __align__(16) int4 g_spanMD[BATCH * MSPAN];  // (S, E, outSlot, pad), S/E into g_tok
__device__ int  g_tok[BATCH * SEQ];                     // compact valid-token list

__device__ __forceinline__ int acq_load(const int* p) {
    int v;
    asm volatile("ld.acquire.gpu.b32 %0, [%1];" : "=r"(v) : "l"(p) : "memory");
    return v;
}

// ---------------------------------------------------------------------------
// Tree-fold 4 per-lane partials across the warp in 6 SHFLs; lanes
// {0,8,16,24} write floc {0,1,2,3}.
// ---------------------------------------------------------------------------
__device__ __forceinline__ void fold_write(
    const float sc[4], float* __restrict__ dst, int lane)
{
    float send0 = (lane & 16) ? sc[0] : sc[2];
    float r0 = __shfl_xor_sync(0xffffffffu, send0, 16);
    float n0 = ((lane & 16) ? sc[2] : sc[0]) + r0;
    float send1 = (lane & 16) ? sc[1] : sc[3];
    float r1 = __shfl_xor_sync(0xffffffffu, send1, 16);
    float n1 = ((lane & 16) ? sc[3] : sc[1]) + r1;

    float send = (lane & 8) ? n0 : n1;
    float r = __shfl_xor_sync(0xffffffffu, send, 8);
    float v = ((lane & 8) ? n1 : n0) + r;

    v += __shfl_xor_sync(0xffffffffu, v, 4);
    v += __shfl_xor_sync(0xffffffffu, v, 2);
    v += __shfl_xor_sync(0xffffffffu, v, 1);

    if ((lane & 7) == 0) {
        int floc = (((lane >> 4) & 1) << 1) | ((lane >> 3) & 1);
        dst[floc] = v;
    }
}

// ---------------------------------------------------------------------------
// Accumulate combined contiguous token range [S,E) with boundary M:
// rows with tok-index < M go to F0, the rest to F1. Two rows in flight
// pipelined across the WHOLE pair (one DRAM wait per pair).
// Passing M == E accumulates everything into F0 (single-span mode).
// ---------------------------------------------------------------------------
__device__ __forceinline__ void accum_contig(
    u64 F0[8], u64 F1[8], const float* __restrict__ hidden,
    const int* __restrict__ tok, int S, int M, int E, int lane)
{
    for (int c = S; c < E; c += 32) {
        int t = 0;
        if (c + lane < E) t = __ldg(tok + c + lane);
        int n = E - c; if (n > 32) n = 32;
        int r = 0;
        for (; r + 2 <= n; r += 2) {
            int t0 = __shfl_sync(0xffffffffu, t, r);
            int t1 = __shfl_sync(0xffffffffu, t, r + 1);
            const ulonglong2* h0 =
                reinterpret_cast<const ulonglong2*>(hidden + (size_t)t0 * DIM);
            const ulonglong2* h1 =
                reinterpret_cast<const ulonglong2*>(hidden + (size_t)t1 * DIM);
            ulonglong2 a0 = __ldg(h0 + lane),      a1 = __ldg(h1 + lane);
            ulonglong2 b0 = __ldg(h0 + lane + 32), b1 = __ldg(h1 + lane + 32);
            ulonglong2 c0 = __ldg(h0 + lane + 64), c1 = __ldg(h1 + lane + 64);
            ulonglong2 d0 = __ldg(h0 + lane + 96), d1 = __ldg(h1 + lane + 96);
            if (c + r < M)     { ACC_ROW(F0, a0, b0, c0, d0); }
            else               { ACC_ROW(F1, a0, b0, c0, d0); }
            if (c + r + 1 < M) { ACC_ROW(F0, a1, b1, c1, d1); }
            else               { ACC_ROW(F1, a1, b1, c1, d1); }
        }
        if (r < n) {
            int t0 = __shfl_sync(0xffffffffu, t, r);
            const ulonglong2* h0 =
                reinterpret_cast<const ulonglong2*>(hidden + (size_t)t0 * DIM);
            ulonglong2 a0 = __ldg(h0 + lane);
            ulonglong2 b0 = __ldg(h0 + lane + 32);
            ulonglong2 c0 = __ldg(h0 + lane + 64);
            ulonglong2 d0 = __ldg(h0 + lane + 96);
            if (c + r < M) { ACC_ROW(F0, a0, b0, c0, d0); }
            else           { ACC_ROW(F1, a0, b0, c0, d0); }
        }
    }
}

// ---------------------------------------------------------------------------
// Fused kernel. Blocks 0..63: index row b -> compact valid-token list +
// span ranges. All blocks then consume 2-span tickets with combined
// contiguous accumulation, ticket prefetch, shared-W projection.
// ---------------------------------------------------------------------------
__global__ void __launch_bounds__(256, 3) fused_kernel(
    const float* __restrict__ hidden,
    const float* __restrict__ slot,   // [DIM][NFINE]
    const int*   __restrict__ labels, // flat [BATCH*SEQ]
    const int*   __restrict__ pB,
    const int*   __restrict__ pI,
    float* __restrict__ out)          // [BATCH][MSPAN][NFINE]
{
    __shared__ __align__(16) float Wsh[NFINE * DIM];  // Wsh[f*512 + d], 32KB
    __shared__ int SpanStart[MSPAN];
    __shared__ int wsumA[8], wsumB[8];

    const int tid  = threadIdx.x;
    const int lane = tid & 31;
    const int warp = tid >> 5;

    // ---- phase 0: first 64 blocks index their batch row ----
    if (blockIdx.x < BATCH) {
        const int b = blockIdx.x;
        const int cB = *pB;
        const int cI = *pI;
        const int* row = labels + (size_t)b * SEQ;
        const int s0 = tid * 8;

        int flagB[8], isI[8];
        int cntB = 0;
#pragma unroll
        for (int j = 0; j < 8; j++) {
            int lab = row[s0 + j];
            flagB[j] = (lab == cB) ? 1 : 0;
            isI[j]   = (lab == cI) ? 1 : 0;
            cntB += flagB[j];
        }

        // scan 1: B counts
        int incB = cntB;
#pragma unroll
        for (int o = 1; o < 32; o <<= 1) {
            int v = __shfl_up_sync(0xffffffffu, incB, o);
            if (lane >= o) incB += v;
        }
        if (lane == 31) wsumA[warp] = incB;
        __syncthreads();
        if (tid < 8) {
            int v = wsumA[tid];
#pragma unroll
            for (int o = 1; o < 8; o <<= 1) {
                int u = __shfl_up_sync(0xffu, v, o);
                if (tid >= o) v += u;
            }
            wsumA[tid] = v;
        }
        __syncthreads();
        const int exclB = incB - cntB + (warp > 0 ? wsumA[warp - 1] : 0);
        const int nbtot = wsumA[7];

        // validity with running B count
        int flagV[8];
        int cntV = 0;
        {
            int runB = exclB;
#pragma unroll
            for (int j = 0; j < 8; j++) {
                int v;
                if (flagB[j]) {
                    v = (runB < MSPAN) ? 1 : 0;
                    runB++;
                } else if (isI[j]) {
                    int seg = runB - 1;
                    v = (seg >= 0 && seg < MSPAN) ? 1 : 0;
                } else v = 0;
                flagV[j] = v;
                cntV += v;
            }
        }

        // scan 2: valid counts
        int incV = cntV;
#pragma unroll
        for (int o = 1; o < 32; o <<= 1) {
            int v = __shfl_up_sync(0xffffffffu, incV, o);
            if (lane >= o) incV += v;
        }
        if (lane == 31) wsumB[warp] = incV;
        __syncthreads();
        if (tid < 8) {
            int v = wsumB[tid];
#pragma unroll
            for (int o = 1; o < 8; o <<= 1) {
                int u = __shfl_up_sync(0xffu, v, o);
                if (tid >= o) v += u;
            }
            wsumB[tid] = v;
        }
        __syncthreads();
        const int exclV = incV - cntV + (warp > 0 ? wsumB[warp - 1] : 0);
        const int nvtot = wsumB[7];

        // emit tokens + span starts
        {
            int runB = exclB;
            int vidx = exclV;
#pragma unroll
            for (int j = 0; j < 8; j++) {
                if (flagB[j]) {
                    if (runB < MSPAN) SpanStart[runB] = vidx;
                    runB++;
                }
                if (flagV[j]) {
                    g_tok[b * SEQ + vidx] = b * SEQ + s0 + j;
                    vidx++;
                }
            }
        }
        __syncthreads();

        const int n = nbtot < MSPAN ? nbtot : MSPAN;
        __shared__ int s_base;
        if (tid == 0) s_base = atomicAdd(&g_ctr[0], n);
        __syncthreads();
        const int base = s_base;
        for (int k = tid; k < n; k += 256) {
            int S = SpanStart[k];
            int E = (k + 1 < n) ? SpanStart[k + 1] : nvtot;
            g_spanMD[base + k] =
                make_int4(b * SEQ + S, b * SEQ + E, b * MSPAN + k, 0);
        }
        __syncthreads();
        if (tid == 0) {
            __threadfence();
            atomicAdd(&g_ctr[3], 1);
        }
    }

    // ---- stage W transposed while indexers finish ----
    for (int i = tid; i < DIM * NFINE; i += 256) {
        int d = i >> 4;
        int f = i & 15;
        Wsh[f * DIM + d] = slot[i];
    }

    // ---- wait until all 64 indexer blocks are done ----
    if (tid == 0) {
        while (acq_load(&g_ctr[3]) < BATCH) { }
    }
    __syncthreads();

    const ulonglong2* W2 = reinterpret_cast<const ulonglong2*>(Wsh);
    const int total = g_ctr[0];

    // ---- main loop: 2 spans per ticket, ticket prefetched ----
    int tk;
    if (lane == 0) tk = atomicAdd(&g_ctr[1], 2);
    for (;;) {
        const int i = __shfl_sync(0xffffffffu, tk, 0);
        if (i >= total) break;
        if (lane == 0) tk = atomicAdd(&g_ctr[1], 2);  // prefetch next ticket

        const bool v1 = (i + 1 < total);
        int4 m0 = __ldg(g_spanMD + i);
        int4 m1 = v1 ? __ldg(g_spanMD + i + 1) : make_int4(m0.y, m0.y, 0, 0);
        const int O0 = m0.z;
        const int O1 = m1.z;

        u64 F0[8], F1[8];
#pragma unroll
        for (int k = 0; k < 8; k++) { F0[k] = 0ull; F1[k] = 0ull; }

        if (m1.x == m0.y) {
            // contiguous pair (same batch row): one combined stream
            accum_contig(F0, F1, hidden, g_tok, m0.x, m0.y, m1.y, lane);
        } else {
            accum_contig(F0, F1, hidden, g_tok, m0.x, m0.y, m0.y, lane);
            if (v1)
                accum_contig(F1, F0, hidden, g_tok, m1.x, m1.y, m1.y, lane);
        }

        // projection: 4 groups of 4 filters; W LDS shared by both spans
#pragma unroll
        for (int g = 0; g < 4; g++) {
            float sc0[4], sc1[4];
#pragma unroll
            for (int jj = 0; jj < 4; jj++) {
                const int f = 4 * g + jj;
                ulonglong2 wa = W2[f * 128 + lane];
                ulonglong2 wb = W2[f * 128 + lane + 32];
                ulonglong2 wc = W2[f * 128 + lane + 64];
                ulonglong2 wd = W2[f * 128 + lane + 96];
                u64 a0 = 0ull, a1 = 0ull;
                FMA2(a0, F0[0], wa.x, a0);  FMA2(a1, F1[0], wa.x, a1);
                FMA2(a0, F0[1], wa.y, a0);  FMA2(a1, F1[1], wa.y, a1);
                FMA2(a0, F0[2], wb.x, a0);  FMA2(a1, F1[2], wb.x, a1);
                FMA2(a0, F0[3], wb.y, a0);  FMA2(a1, F1[3], wb.y, a1);
                FMA2(a0, F0[4], wc.x, a0);  FMA2(a1, F1[4], wc.x, a1);
                FMA2(a0, F0[5], wc.y, a0);  FMA2(a1, F1[5], wc.y, a1);
                FMA2(a0, F0[6], wd.x, a0);  FMA2(a1, F1[6], wd.x, a1);
                FMA2(a0, F0[7], wd.y, a0);  FMA2(a1, F1[7], wd.y, a1);
                float2 p0 = *reinterpret_cast<float2*>(&a0);
                float2 p1 = *reinterpret_cast<float2*>(&a1);
                sc0[jj] = p0.x + p0.y;
                sc1[jj] = p1.x + p1.y;
            }
            fold_write(sc0, out + (size_t)O0 * NFINE + 4 * g, lane);
            if (v1) fold_write(sc1, out + (size_t)O1 * NFINE + 4 * g, lane);
        }
    }
}

extern "C" void kernel_launch(void* const* d_in, const int* in_sizes, int n_in,
                              void* d_out, int out_size)
{
    const float* hidden = (const float*)d_in[0];
    const float* slot   = (const float*)d_in[1];
    const int*   labels = (const int*)d_in[2];
    const int*   pB     = (const int*)d_in[3];
    const int*   pI     = (const int*)d_in[4];
    float* out = (float*)d_out;

    void* ctr_ptr = nullptr;
    cudaGetSymbolAddress(&ctr_ptr, g_ctr);
    cudaMemsetAsync(ctr_ptr, 0, 4 * sizeof(int), 0);
    cudaMemsetAsync(out, 0, (size_t)out_size * sizeof(float), 0);

    fused_kernel<<<GRID, 256>>>(hidden, slot, labels, pB, pI, out);
}

// round 14
// speedup vs baseline: 1.0189x; 1.0189x over previous
#include <cuda_runtime.h>
#include <cstddef>
#include <cstdint>

#define BATCH 64
#define SEQ   2048
#define DIM   512
#define NFINE 16
#define MSPAN 512
#define GRID  (148 * 3)

typedef unsigned long long u64;

// Blackwell packed fp32x2 math (SASS FFMA2/FADD2) — PTX-only.
#define FMA2(d,a,b,c) asm("fma.rn.f32x2 %0, %1, %2, %3;" : "=l"(d) : "l"(a), "l"(b), "l"(c))
#define ADD2(d,a,b)   asm("add.rn.f32x2 %0, %1, %2;" : "=l"(d) : "l"(a), "l"(b))

// [0]=total spans, [1]=work ticket, [2]=unused, [3]=index-done counter
__device__ int  g_ctr[4];
__device__ __align__(16) int4 g_spanMD[BATCH * MSPAN];  // (S, E, outSlot, pad) into g_tok
__device__ int  g_tok[BATCH * SEQ];                     // compact valid-token list

__device__ __forceinline__ int acq_load(const int* p) {
    int v;
    asm volatile("ld.acquire.gpu.b32 %0, [%1];" : "=r"(v) : "l"(p) : "memory");
    return v;
}

// ---------------------------------------------------------------------------
// Tree-fold 4 per-lane partials across the warp in 6 SHFLs; lanes
// {0,8,16,24} write floc {0,1,2,3}.
// ---------------------------------------------------------------------------
__device__ __forceinline__ void fold_write(
    const float sc[4], float* __restrict__ dst, int lane)
{
    float send0 = (lane & 16) ? sc[0] : sc[2];
    float r0 = __shfl_xor_sync(0xffffffffu, send0, 16);
    float n0 = ((lane & 16) ? sc[2] : sc[0]) + r0;
    float send1 = (lane & 16) ? sc[1] : sc[3];
    float r1 = __shfl_xor_sync(0xffffffffu, send1, 16);
    float n1 = ((lane & 16) ? sc[3] : sc[1]) + r1;

    float send = (lane & 8) ? n0 : n1;
    float r = __shfl_xor_sync(0xffffffffu, send, 8);
    float v = ((lane & 8) ? n1 : n0) + r;

    v += __shfl_xor_sync(0xffffffffu, v, 4);
    v += __shfl_xor_sync(0xffffffffu, v, 2);
    v += __shfl_xor_sync(0xffffffffu, v, 1);

    if ((lane & 7) == 0) {
        int floc = (((lane >> 4) & 1) << 1) | ((lane >> 3) & 1);
        dst[floc] = v;
    }
}

// ---------------------------------------------------------------------------
// Segment-sum over a precomputed token range [S,E) of g_tok. Counted loop,
// two rows in flight (8 independent LDG.128). Unpredicated accumulate.
// ---------------------------------------------------------------------------
__device__ __forceinline__ void accum_span_list(
    u64 F[8], const float* __restrict__ hidden,
    const int* __restrict__ tok, int S, int E, int lane)
{
#pragma unroll
    for (int k = 0; k < 8; k++) F[k] = 0ull;

    for (int c = S; c < E; c += 32) {
        int t = 0;
        if (c + lane < E) t = __ldg(tok + c + lane);
        int n = E - c; if (n > 32) n = 32;
        int r = 0;
        for (; r + 2 <= n; r += 2) {
            int t0 = __shfl_sync(0xffffffffu, t, r);
            int t1 = __shfl_sync(0xffffffffu, t, r + 1);
            const ulonglong2* h0 =
                reinterpret_cast<const ulonglong2*>(hidden + (size_t)t0 * DIM);
            const ulonglong2* h1 =
                reinterpret_cast<const ulonglong2*>(hidden + (size_t)t1 * DIM);
            ulonglong2 a0 = __ldg(h0 + lane),      a1 = __ldg(h1 + lane);
            ulonglong2 b0 = __ldg(h0 + lane + 32), b1 = __ldg(h1 + lane + 32);
            ulonglong2 c0 = __ldg(h0 + lane + 64), c1 = __ldg(h1 + lane + 64);
            ulonglong2 d0 = __ldg(h0 + lane + 96), d1 = __ldg(h1 + lane + 96);
            ADD2(F[0], F[0], a0.x); ADD2(F[1], F[1], a0.y);
            ADD2(F[2], F[2], b0.x); ADD2(F[3], F[3], b0.y);
            ADD2(F[4], F[4], c0.x); ADD2(F[5], F[5], c0.y);
            ADD2(F[6], F[6], d0.x); ADD2(F[7], F[7], d0.y);
            ADD2(F[0], F[0], a1.x); ADD2(F[1], F[1], a1.y);
            ADD2(F[2], F[2], b1.x); ADD2(F[3], F[3], b1.y);
            ADD2(F[4], F[4], c1.x); ADD2(F[5], F[5], c1.y);
            ADD2(F[6], F[6], d1.x); ADD2(F[7], F[7], d1.y);
        }
        if (r < n) {
            int t0 = __shfl_sync(0xffffffffu, t, r);
            const ulonglong2* h0 =
                reinterpret_cast<const ulonglong2*>(hidden + (size_t)t0 * DIM);
            ulonglong2 a0 = __ldg(h0 + lane);
            ulonglong2 b0 = __ldg(h0 + lane + 32);
            ulonglong2 c0 = __ldg(h0 + lane + 64);
            ulonglong2 d0 = __ldg(h0 + lane + 96);
            ADD2(F[0], F[0], a0.x); ADD2(F[1], F[1], a0.y);
            ADD2(F[2], F[2], b0.x); ADD2(F[3], F[3], b0.y);
            ADD2(F[4], F[4], c0.x); ADD2(F[5], F[5], c0.y);
            ADD2(F[6], F[6], d0.x); ADD2(F[7], F[7], d0.y);
        }
    }
}

// ---------------------------------------------------------------------------
// Fused kernel. Blocks 0..63: index row b -> compact valid-token list +
// span ranges. All blocks then consume 2-span tickets (prefetched):
// counted dual-row segment sum + shared-W projection.
// ---------------------------------------------------------------------------
__global__ void __launch_bounds__(256, 3) fused_kernel(
    const float* __restrict__ hidden,
    const float* __restrict__ slot,   // [DIM][NFINE]
    const int*   __restrict__ labels, // flat [BATCH*SEQ]
    const int*   __restrict__ pB,
    const int*   __restrict__ pI,
    float* __restrict__ out)          // [BATCH][MSPAN][NFINE]
{
    __shared__ __align__(16) float Wsh[NFINE * DIM];  // Wsh[f*512 + d], 32KB
    __shared__ int SpanStart[MSPAN];
    __shared__ int wsumA[8], wsumB[8];

    const int tid  = threadIdx.x;
    const int lane = tid & 31;
    const int warp = tid >> 5;

    // ---- phase 0: first 64 blocks index their batch row ----
    if (blockIdx.x < BATCH) {
        const int b = blockIdx.x;
        const int cB = *pB;
        const int cI = *pI;
        const int* row = labels + (size_t)b * SEQ;
        const int s0 = tid * 8;

        int flagB[8], isI[8];
        int cntB = 0;
#pragma unroll
        for (int j = 0; j < 8; j++) {
            int lab = row[s0 + j];
            flagB[j] = (lab == cB) ? 1 : 0;
            isI[j]   = (lab == cI) ? 1 : 0;
            cntB += flagB[j];
        }

        // scan 1: B counts
        int incB = cntB;
#pragma unroll
        for (int o = 1; o < 32; o <<= 1) {
            int v = __shfl_up_sync(0xffffffffu, incB, o);
            if (lane >= o) incB += v;
        }
        if (lane == 31) wsumA[warp] = incB;
        __syncthreads();
        if (tid < 8) {
            int v = wsumA[tid];
#pragma unroll
            for (int o = 1; o < 8; o <<= 1) {
                int u = __shfl_up_sync(0xffu, v, o);
                if (tid >= o) v += u;
            }
            wsumA[tid] = v;
        }
        __syncthreads();
        const int exclB = incB - cntB + (warp > 0 ? wsumA[warp - 1] : 0);
        const int nbtot = wsumA[7];

        // validity with running B count
        int flagV[8];
        int cntV = 0;
        {
            int runB = exclB;
#pragma unroll
            for (int j = 0; j < 8; j++) {
                int v;
                if (flagB[j]) {
                    v = (runB < MSPAN) ? 1 : 0;
                    runB++;
                } else if (isI[j]) {
                    int seg = runB - 1;
                    v = (seg >= 0 && seg < MSPAN) ? 1 : 0;
                } else v = 0;
                flagV[j] = v;
                cntV += v;
            }
        }

        // scan 2: valid counts
        int incV = cntV;
#pragma unroll
        for (int o = 1; o < 32; o <<= 1) {
            int v = __shfl_up_sync(0xffffffffu, incV, o);
            if (lane >= o) incV += v;
        }
        if (lane == 31) wsumB[warp] = incV;
        __syncthreads();
        if (tid < 8) {
            int v = wsumB[tid];
#pragma unroll
            for (int o = 1; o < 8; o <<= 1) {
                int u = __shfl_up_sync(0xffu, v, o);
                if (tid >= o) v += u;
            }
            wsumB[tid] = v;
        }
        __syncthreads();
        const int exclV = incV - cntV + (warp > 0 ? wsumB[warp - 1] : 0);
        const int nvtot = wsumB[7];

        // emit tokens + span starts
        {
            int runB = exclB;
            int vidx = exclV;
#pragma unroll
            for (int j = 0; j < 8; j++) {
                if (flagB[j]) {
                    if (runB < MSPAN) SpanStart[runB] = vidx;
                    runB++;
                }
                if (flagV[j]) {
                    g_tok[b * SEQ + vidx] = b * SEQ + s0 + j;
                    vidx++;
                }
            }
        }
        __syncthreads();

        const int n = nbtot < MSPAN ? nbtot : MSPAN;
        __shared__ int s_base;
        if (tid == 0) s_base = atomicAdd(&g_ctr[0], n);
        __syncthreads();
        const int base = s_base;
        for (int k = tid; k < n; k += 256) {
            int S = SpanStart[k];
            int E = (k + 1 < n) ? SpanStart[k + 1] : nvtot;
            g_spanMD[base + k] =
                make_int4(b * SEQ + S, b * SEQ + E, b * MSPAN + k, 0);
        }
        __syncthreads();
        if (tid == 0) {
            __threadfence();
            atomicAdd(&g_ctr[3], 1);
        }
    }

    // ---- stage W transposed while indexers finish ----
    for (int i = tid; i < DIM * NFINE; i += 256) {
        int d = i >> 4;
        int f = i & 15;
        Wsh[f * DIM + d] = slot[i];
    }

    // ---- wait until all 64 indexer blocks are done ----
    if (tid == 0) {
        while (acq_load(&g_ctr[3]) < BATCH) { }
    }
    __syncthreads();

    const ulonglong2* W2 = reinterpret_cast<const ulonglong2*>(Wsh);
    const int total = g_ctr[0];

    // ---- main loop: 2 spans per ticket, ticket prefetched ----
    int tk;
    if (lane == 0) tk = atomicAdd(&g_ctr[1], 2);
    for (;;) {
        const int i = __shfl_sync(0xffffffffu, tk, 0);
        if (i >= total) break;
        if (lane == 0) tk = atomicAdd(&g_ctr[1], 2);  // prefetch next ticket

        const bool v1 = (i + 1 < total);
        int4 m0 = __ldg(g_spanMD + i);
        int4 m1 = v1 ? __ldg(g_spanMD + i + 1) : make_int4(0, 0, 0, 0);
        const int O0 = m0.z;
        const int O1 = m1.z;

        u64 F0[8], F1[8];
        accum_span_list(F0, hidden, g_tok, m0.x, m0.y, lane);
        if (v1) {
            accum_span_list(F1, hidden, g_tok, m1.x, m1.y, lane);
        } else {
#pragma unroll
            for (int k = 0; k < 8; k++) F1[k] = 0ull;
        }

        // projection: 4 groups of 4 filters; W LDS shared by both spans
#pragma unroll
        for (int g = 0; g < 4; g++) {
            float sc0[4], sc1[4];
#pragma unroll
            for (int jj = 0; jj < 4; jj++) {
                const int f = 4 * g + jj;
                ulonglong2 wa = W2[f * 128 + lane];
                ulonglong2 wb = W2[f * 128 + lane + 32];
                ulonglong2 wc = W2[f * 128 + lane + 64];
                ulonglong2 wd = W2[f * 128 + lane + 96];
                u64 a0 = 0ull, a1 = 0ull;
                FMA2(a0, F0[0], wa.x, a0);  FMA2(a1, F1[0], wa.x, a1);
                FMA2(a0, F0[1], wa.y, a0);  FMA2(a1, F1[1], wa.y, a1);
                FMA2(a0, F0[2], wb.x, a0);  FMA2(a1, F1[2], wb.x, a1);
                FMA2(a0, F0[3], wb.y, a0);  FMA2(a1, F1[3], wb.y, a1);
                FMA2(a0, F0[4], wc.x, a0);  FMA2(a1, F1[4], wc.x, a1);
                FMA2(a0, F0[5], wc.y, a0);  FMA2(a1, F1[5], wc.y, a1);
                FMA2(a0, F0[6], wd.x, a0);  FMA2(a1, F1[6], wd.x, a1);
                FMA2(a0, F0[7], wd.y, a0);  FMA2(a1, F1[7], wd.y, a1);
                float2 p0 = *reinterpret_cast<float2*>(&a0);
                float2 p1 = *reinterpret_cast<float2*>(&a1);
                sc0[jj] = p0.x + p0.y;
                sc1[jj] = p1.x + p1.y;
            }
            fold_write(sc0, out + (size_t)O0 * NFINE + 4 * g, lane);
            if (v1) fold_write(sc1, out + (size_t)O1 * NFINE + 4 * g, lane);
        }
    }
}

extern "C" void kernel_launch(void* const* d_in, const int* in_sizes, int n_in,
                              void* d_out, int out_size)
{
    const float* hidden = (const float*)d_in[0];
    const float* slot   = (const float*)d_in[1];
    const int*   labels = (const int*)d_in[2];
    const int*   pB     = (const int*)d_in[3];
    const int*   pI     = (const int*)d_in[4];
    float* out = (float*)d_out;

    void* ctr_ptr = nullptr;
    cudaGetSymbolAddress(&ctr_ptr, g_ctr);
    cudaMemsetAsync(ctr_ptr, 0, 4 * sizeof(int), 0);
    cudaMemsetAsync(out, 0, (size_t)out_size * sizeof(float), 0);

    fused_kernel<<<GRID, 256>>>(hidden, slot, labels, pB, pI, out);
}

// round 15
// speedup vs baseline: 1.0811x; 1.0611x over previous
#include <cuda_runtime.h>
#include <cstddef>
#include <cstdint>

#define BATCH 64
#define SEQ   2048
#define DIM   512
#define NFINE 16
#define MSPAN 512
#define GRID  (148 * 3)

typedef unsigned long long u64;

// Blackwell packed fp32x2 math (SASS FFMA2/FADD2) — PTX-only.
#define FMA2(d,a,b,c) asm("fma.rn.f32x2 %0, %1, %2, %3;" : "=l"(d) : "l"(a), "l"(b), "l"(c))
#define ADD2(d,a,b)   asm("add.rn.f32x2 %0, %1, %2;" : "=l"(d) : "l"(a), "l"(b))

// [0]=total spans, [1]=work ticket, [2]=unused, [3]=index-done counter
__device__ int  g_ctr[4];
__device__ __align__(16) int4 g_spanMD[BATCH * MSPAN];  // (S, E, outSlot, pad) into g_tok
__device__ int  g_tok[BATCH * SEQ];                     // compact valid-token list

__device__ __forceinline__ int acq_load(const int* p) {
    int v;
    asm volatile("ld.acquire.gpu.b32 %0, [%1];" : "=r"(v) : "l"(p) : "memory");
    return v;
}

// ---------------------------------------------------------------------------
// Tree-fold 4 per-lane partials across the warp in 6 SHFLs; lanes
// {0,8,16,24} write floc {0,1,2,3}.
// ---------------------------------------------------------------------------
__device__ __forceinline__ void fold_write(
    const float sc[4], float* __restrict__ dst, int lane)
{
    float send0 = (lane & 16) ? sc[0] : sc[2];
    float r0 = __shfl_xor_sync(0xffffffffu, send0, 16);
    float n0 = ((lane & 16) ? sc[2] : sc[0]) + r0;
    float send1 = (lane & 16) ? sc[1] : sc[3];
    float r1 = __shfl_xor_sync(0xffffffffu, send1, 16);
    float n1 = ((lane & 16) ? sc[3] : sc[1]) + r1;

    float send = (lane & 8) ? n0 : n1;
    float r = __shfl_xor_sync(0xffffffffu, send, 8);
    float v = ((lane & 8) ? n1 : n0) + r;

    v += __shfl_xor_sync(0xffffffffu, v, 4);
    v += __shfl_xor_sync(0xffffffffu, v, 2);
    v += __shfl_xor_sync(0xffffffffu, v, 1);

    if ((lane & 7) == 0) {
        int floc = (((lane >> 4) & 1) << 1) | ((lane >> 3) & 1);
        dst[floc] = v;
    }
}

// ---------------------------------------------------------------------------
// Segment-sum over a precomputed token range [S,E) of g_tok. Counted loop,
// two rows in flight (8 independent LDG.128). Unpredicated accumulate.
// ---------------------------------------------------------------------------
__device__ __forceinline__ void accum_span_list(
    u64 F[8], const float* __restrict__ hidden,
    const int* __restrict__ tok, int S, int E, int lane)
{
#pragma unroll
    for (int k = 0; k < 8; k++) F[k] = 0ull;

    for (int c = S; c < E; c += 32) {
        int t = 0;
        if (c + lane < E) t = __ldg(tok + c + lane);
        int n = E - c; if (n > 32) n = 32;
        int r = 0;
        for (; r + 2 <= n; r += 2) {
            int t0 = __shfl_sync(0xffffffffu, t, r);
            int t1 = __shfl_sync(0xffffffffu, t, r + 1);
            const ulonglong2* h0 =
                reinterpret_cast<const ulonglong2*>(hidden + (size_t)t0 * DIM);
            const ulonglong2* h1 =
                reinterpret_cast<const ulonglong2*>(hidden + (size_t)t1 * DIM);
            ulonglong2 a0 = __ldg(h0 + lane),      a1 = __ldg(h1 + lane);
            ulonglong2 b0 = __ldg(h0 + lane + 32), b1 = __ldg(h1 + lane + 32);
            ulonglong2 c0 = __ldg(h0 + lane + 64), c1 = __ldg(h1 + lane + 64);
            ulonglong2 d0 = __ldg(h0 + lane + 96), d1 = __ldg(h1 + lane + 96);
            ADD2(F[0], F[0], a0.x); ADD2(F[1], F[1], a0.y);
            ADD2(F[2], F[2], b0.x); ADD2(F[3], F[3], b0.y);
            ADD2(F[4], F[4], c0.x); ADD2(F[5], F[5], c0.y);
            ADD2(F[6], F[6], d0.x); ADD2(F[7], F[7], d0.y);
            ADD2(F[0], F[0], a1.x); ADD2(F[1], F[1], a1.y);
            ADD2(F[2], F[2], b1.x); ADD2(F[3], F[3], b1.y);
            ADD2(F[4], F[4], c1.x); ADD2(F[5], F[5], c1.y);
            ADD2(F[6], F[6], d1.x); ADD2(F[7], F[7], d1.y);
        }
        if (r < n) {
            int t0 = __shfl_sync(0xffffffffu, t, r);
            const ulonglong2* h0 =
                reinterpret_cast<const ulonglong2*>(hidden + (size_t)t0 * DIM);
            ulonglong2 a0 = __ldg(h0 + lane);
            ulonglong2 b0 = __ldg(h0 + lane + 32);
            ulonglong2 c0 = __ldg(h0 + lane + 64);
            ulonglong2 d0 = __ldg(h0 + lane + 96);
            ADD2(F[0], F[0], a0.x); ADD2(F[1], F[1], a0.y);
            ADD2(F[2], F[2], b0.x); ADD2(F[3], F[3], b0.y);
            ADD2(F[4], F[4], c0.x); ADD2(F[5], F[5], c0.y);
            ADD2(F[6], F[6], d0.x); ADD2(F[7], F[7], d0.y);
        }
    }
}

// ---------------------------------------------------------------------------
// Fused kernel. Blocks 0..63: index row b -> compact valid-token list +
// span ranges, publish, then ZERO the row's invalid output slots (overlapped
// with consumers). All blocks consume 2-span tickets (prefetched): counted
// dual-row segment sum + shared-W projection. No host-side out memset.
// ---------------------------------------------------------------------------
__global__ void __launch_bounds__(256, 3) fused_kernel(
    const float* __restrict__ hidden,
    const float* __restrict__ slot,   // [DIM][NFINE]
    const int*   __restrict__ labels, // flat [BATCH*SEQ]
    const int*   __restrict__ pB,
    const int*   __restrict__ pI,
    float* __restrict__ out)          // [BATCH][MSPAN][NFINE]
{
    __shared__ __align__(16) float Wsh[NFINE * DIM];  // Wsh[f*512 + d], 32KB
    __shared__ int SpanStart[MSPAN];
    __shared__ int wsumA[8], wsumB[8];

    const int tid  = threadIdx.x;
    const int lane = tid & 31;
    const int warp = tid >> 5;

    // ---- phase 0: first 64 blocks index their batch row ----
    if (blockIdx.x < BATCH) {
        const int b = blockIdx.x;
        const int cB = *pB;
        const int cI = *pI;
        const int* row = labels + (size_t)b * SEQ;
        const int s0 = tid * 8;

        int flagB[8], isI[8];
        int cntB = 0;
#pragma unroll
        for (int j = 0; j < 8; j++) {
            int lab = row[s0 + j];
            flagB[j] = (lab == cB) ? 1 : 0;
            isI[j]   = (lab == cI) ? 1 : 0;
            cntB += flagB[j];
        }

        // scan 1: B counts
        int incB = cntB;
#pragma unroll
        for (int o = 1; o < 32; o <<= 1) {
            int v = __shfl_up_sync(0xffffffffu, incB, o);
            if (lane >= o) incB += v;
        }
        if (lane == 31) wsumA[warp] = incB;
        __syncthreads();
        if (tid < 8) {
            int v = wsumA[tid];
#pragma unroll
            for (int o = 1; o < 8; o <<= 1) {
                int u = __shfl_up_sync(0xffu, v, o);
                if (tid >= o) v += u;
            }
            wsumA[tid] = v;
        }
        __syncthreads();
        const int exclB = incB - cntB + (warp > 0 ? wsumA[warp - 1] : 0);
        const int nbtot = wsumA[7];

        // validity with running B count
        int flagV[8];
        int cntV = 0;
        {
            int runB = exclB;
#pragma unroll
            for (int j = 0; j < 8; j++) {
                int v;
                if (flagB[j]) {
                    v = (runB < MSPAN) ? 1 : 0;
                    runB++;
                } else if (isI[j]) {
                    int seg = runB - 1;
                    v = (seg >= 0 && seg < MSPAN) ? 1 : 0;
                } else v = 0;
                flagV[j] = v;
                cntV += v;
            }
        }

        // scan 2: valid counts
        int incV = cntV;
#pragma unroll
        for (int o = 1; o < 32; o <<= 1) {
            int v = __shfl_up_sync(0xffffffffu, incV, o);
            if (lane >= o) incV += v;
        }
        if (lane == 31) wsumB[warp] = incV;
        __syncthreads();
        if (tid < 8) {
            int v = wsumB[tid];
#pragma unroll
            for (int o = 1; o < 8; o <<= 1) {
                int u = __shfl_up_sync(0xffu, v, o);
                if (tid >= o) v += u;
            }
            wsumB[tid] = v;
        }
        __syncthreads();
        const int exclV = incV - cntV + (warp > 0 ? wsumB[warp - 1] : 0);
        const int nvtot = wsumB[7];

        // emit tokens + span starts
        {
            int runB = exclB;
            int vidx = exclV;
#pragma unroll
            for (int j = 0; j < 8; j++) {
                if (flagB[j]) {
                    if (runB < MSPAN) SpanStart[runB] = vidx;
                    runB++;
                }
                if (flagV[j]) {
                    g_tok[b * SEQ + vidx] = b * SEQ + s0 + j;
                    vidx++;
                }
            }
        }
        __syncthreads();

        const int n = nbtot < MSPAN ? nbtot : MSPAN;
        __shared__ int s_base;
        if (tid == 0) s_base = atomicAdd(&g_ctr[0], n);
        __syncthreads();
        const int base = s_base;
        for (int k = tid; k < n; k += 256) {
            int S = SpanStart[k];
            int E = (k + 1 < n) ? SpanStart[k + 1] : nvtot;
            g_spanMD[base + k] =
                make_int4(b * SEQ + S, b * SEQ + E, b * MSPAN + k, 0);
        }
        __syncthreads();
        if (tid == 0) {
            __threadfence();
            atomicAdd(&g_ctr[3], 1);   // publish FIRST so consumers start
        }

        // zero this row's invalid output slots [n, MSPAN) — overlapped
        {
            float4* zbase = reinterpret_cast<float4*>(
                out + ((size_t)b * MSPAN + n) * NFINE);
            const int nz = (MSPAN - n) * (NFINE / 4);
            const float4 z = make_float4(0.f, 0.f, 0.f, 0.f);
            for (int k = tid; k < nz; k += 256) zbase[k] = z;
        }
    }

    // ---- stage W transposed while indexers finish ----
    for (int i = tid; i < DIM * NFINE; i += 256) {
        int d = i >> 4;
        int f = i & 15;
        Wsh[f * DIM + d] = slot[i];
    }

    // ---- wait until all 64 indexer blocks are done ----
    if (tid == 0) {
        while (acq_load(&g_ctr[3]) < BATCH) { }
    }
    __syncthreads();

    const ulonglong2* W2 = reinterpret_cast<const ulonglong2*>(Wsh);
    const int total = g_ctr[0];

    // ---- main loop: 2 spans per ticket, ticket prefetched ----
    int tk;
    if (lane == 0) tk = atomicAdd(&g_ctr[1], 2);
    for (;;) {
        const int i = __shfl_sync(0xffffffffu, tk, 0);
        if (i >= total) break;
        if (lane == 0) tk = atomicAdd(&g_ctr[1], 2);  // prefetch next ticket

        const bool v1 = (i + 1 < total);
        int4 m0 = __ldg(g_spanMD + i);
        int4 m1 = v1 ? __ldg(g_spanMD + i + 1) : make_int4(0, 0, 0, 0);
        const int O0 = m0.z;
        const int O1 = m1.z;

        u64 F0[8], F1[8];
        accum_span_list(F0, hidden, g_tok, m0.x, m0.y, lane);
        if (v1) {
            accum_span_list(F1, hidden, g_tok, m1.x, m1.y, lane);
        } else {
#pragma unroll
            for (int k = 0; k < 8; k++) F1[k] = 0ull;
        }

        // projection: 4 groups of 4 filters; W LDS shared by both spans
#pragma unroll
        for (int g = 0; g < 4; g++) {
            float sc0[4], sc1[4];
#pragma unroll
            for (int jj = 0; jj < 4; jj++) {
                const int f = 4 * g + jj;
                ulonglong2 wa = W2[f * 128 + lane];
                ulonglong2 wb = W2[f * 128 + lane + 32];
                ulonglong2 wc = W2[f * 128 + lane + 64];
                ulonglong2 wd = W2[f * 128 + lane + 96];
                u64 a0 = 0ull, a1 = 0ull;
                FMA2(a0, F0[0], wa.x, a0);  FMA2(a1, F1[0], wa.x, a1);
                FMA2(a0, F0[1], wa.y, a0);  FMA2(a1, F1[1], wa.y, a1);
                FMA2(a0, F0[2], wb.x, a0);  FMA2(a1, F1[2], wb.x, a1);
                FMA2(a0, F0[3], wb.y, a0);  FMA2(a1, F1[3], wb.y, a1);
                FMA2(a0, F0[4], wc.x, a0);  FMA2(a1, F1[4], wc.x, a1);
                FMA2(a0, F0[5], wc.y, a0);  FMA2(a1, F1[5], wc.y, a1);
                FMA2(a0, F0[6], wd.x, a0);  FMA2(a1, F1[6], wd.x, a1);
                FMA2(a0, F0[7], wd.y, a0);  FMA2(a1, F1[7], wd.y, a1);
                float2 p0 = *reinterpret_cast<float2*>(&a0);
                float2 p1 = *reinterpret_cast<float2*>(&a1);
                sc0[jj] = p0.x + p0.y;
                sc1[jj] = p1.x + p1.y;
            }
            fold_write(sc0, out + (size_t)O0 * NFINE + 4 * g, lane);
            if (v1) fold_write(sc1, out + (size_t)O1 * NFINE + 4 * g, lane);
        }
    }
}

extern "C" void kernel_launch(void* const* d_in, const int* in_sizes, int n_in,
                              void* d_out, int out_size)
{
    const float* hidden = (const float*)d_in[0];
    const float* slot   = (const float*)d_in[1];
    const int*   labels = (const int*)d_in[2];
    const int*   pB     = (const int*)d_in[3];
    const int*   pI     = (const int*)d_in[4];
    float* out = (float*)d_out;

    void* ctr_ptr = nullptr;
    cudaGetSymbolAddress(&ctr_ptr, g_ctr);
    cudaMemsetAsync(ctr_ptr, 0, 4 * sizeof(int), 0);
    // NOTE: no out memset — kernel writes every output element
    // (valid spans via fold_write, invalid slots zeroed by indexer blocks).

    fused_kernel<<<GRID, 256>>>(hidden, slot, labels, pB, pI, out);
}